// round 16
// baseline (speedup 1.0000x reference)
#include <cuda_runtime.h>
#include <cuda_bf16.h>
#include <cstdint>

#define T_ 12
#define N_ 10000
#define E_ 160000
#define P_ 30000
#define DIN_ 128
#define H_ 64
#define NG 24            // 2*T graphs
#define M_ (NG * N_)     // 240000 rows
#define NE_ALL (NG * E_) // 3,840,000 edges
#define HB 8             // hist blocks per graph
#define EPB (E_ / HB)    // 20000 edges per hist block

#define NTILES (M_ / 128)     // 1875
#define TILES_A 938           // rows ..120063  (covers graphs 0..11)
#define TILES_B1 469          // rows ..180095  (covers graphs 12..17)
#define TILES_B2 312          // rows ..220031  (covers graphs 18..21)
#define TILES_B3 (NTILES - TILES_A - TILES_B1 - TILES_B2)   // 156

typedef unsigned long long u64;

// Scratch (allocation-free rule: __device__ globals)
__device__ float g_xp[(size_t)M_ * 128];   // xp = x @ [w_self | w_neigh]
__device__ float g_acc[(size_t)M_ * 64];   // normalized h
__device__ int   g_deg[M_];
__device__ int   g_off[M_];                // CSR start (global, includes g*E_ base)
__device__ int   g_rank[NE_ALL];           // final slot rank of edge within its dst bucket
__device__ int   g_elist[NE_ALL];          // src node id per CSR slot
__device__ uint32_t g_Bt[128 * 128];       // B^T as [n][k], tf32-rounded bits

__device__ __forceinline__ uint32_t tf32_rna(float f) {
    uint32_t u;
    asm("cvt.rna.tf32.f32 %0, %1;" : "=r"(u) : "f"(f));
    return u;
}

// ---------------------------------------------------------------------------
// B prep: g_Bt[n][k] = tf32(W[k][n])
// ---------------------------------------------------------------------------
__global__ void b_prep(const float* __restrict__ w_self,
                       const float* __restrict__ w_neigh) {
    int idx = blockIdx.x * blockDim.x + threadIdx.x;   // 0..16383
    int n = idx >> 7;
    int k = idx & 127;
    const float* wsrc = (n < 64) ? (w_self + n) : (w_neigh + (n - 64));
    g_Bt[n * 128 + k] = tf32_rna(wsrc[k * 64]);
}

// ---------------------------------------------------------------------------
// tf32 mma.sync GEMM: 128x128 tile/CTA, 8 warps, warp tile 32x64,
// k-chunk (64) double-buffered (R15 proven, 43.5us/938 tiles).
// ---------------------------------------------------------------------------
#define CH_STR 68
#define SMEM_GEMM (4 * 128 * CH_STR * 4)   // 139264 B

__device__ __forceinline__ void compute_chunk(
    const uint32_t* __restrict__ As, const uint32_t* __restrict__ Bs,
    float acc[2][8][4], int wrow, int wcol, int lq, int lr) {
    #pragma unroll
    for (int ks = 0; ks < 8; ks++) {
        const int kc = ks * 8 + lr;
        uint32_t a[2][4];
        #pragma unroll
        for (int m = 0; m < 2; m++) {
            int rbase = wrow + m * 16 + lq;
            a[m][0] = As[rbase * CH_STR + kc];
            a[m][1] = As[(rbase + 8) * CH_STR + kc];
            a[m][2] = As[rbase * CH_STR + kc + 4];
            a[m][3] = As[(rbase + 8) * CH_STR + kc + 4];
        }
        uint32_t b[8][2];
        #pragma unroll
        for (int n = 0; n < 8; n++) {
            int nrow = wcol + n * 8 + lq;
            b[n][0] = Bs[nrow * CH_STR + kc];
            b[n][1] = Bs[nrow * CH_STR + kc + 4];
        }
        #pragma unroll
        for (int m = 0; m < 2; m++)
            #pragma unroll
            for (int n = 0; n < 8; n++) {
                asm volatile(
                    "mma.sync.aligned.m16n8k8.row.col.f32.tf32.tf32.f32 "
                    "{%0,%1,%2,%3}, {%4,%5,%6,%7}, {%8,%9}, {%0,%1,%2,%3};"
                    : "+f"(acc[m][n][0]), "+f"(acc[m][n][1]),
                      "+f"(acc[m][n][2]), "+f"(acc[m][n][3])
                    : "r"(a[m][0]), "r"(a[m][1]), "r"(a[m][2]), "r"(a[m][3]),
                      "r"(b[n][0]), "r"(b[n][1]));
            }
    }
}

__global__ __launch_bounds__(256, 1)
void gemm_mma(const float* __restrict__ x, int tile0) {
    extern __shared__ uint32_t smem[];
    uint32_t* As0 = smem;
    uint32_t* As1 = smem + 128 * CH_STR;
    uint32_t* Bs0 = smem + 2 * 128 * CH_STR;
    uint32_t* Bs1 = smem + 3 * 128 * CH_STR;
    const int tid = threadIdx.x;
    const int wid = tid >> 5;
    const int lane = tid & 31;
    const int R0 = (tile0 + blockIdx.x) * 128;

    const float4* x4 = reinterpret_cast<const float4*>(x) + (size_t)R0 * 32;

    {
        const uint4* b4 = reinterpret_cast<const uint4*>(g_Bt);
        #pragma unroll
        for (int i = 0; i < 16; i++) {
            int idx = tid + i * 256;
            int n = idx >> 5;
            int c4 = idx & 31;
            uint4 v = b4[idx];
            uint32_t* dst = (c4 < 16) ? Bs0 : Bs1;
            *reinterpret_cast<uint4*>(dst + n * CH_STR + (c4 & 15) * 4) = v;
        }
    }
    {
        #pragma unroll
        for (int i = 0; i < 8; i++) {
            int idx = tid + i * 256;
            int r = idx >> 4;
            int c4 = idx & 15;
            float4 v = x4[r * 32 + c4];
            uint4 u;
            u.x = tf32_rna(v.x); u.y = tf32_rna(v.y);
            u.z = tf32_rna(v.z); u.w = tf32_rna(v.w);
            *reinterpret_cast<uint4*>(As0 + r * CH_STR + c4 * 4) = u;
        }
    }
    __syncthreads();

    float4 pf[8];
    #pragma unroll
    for (int i = 0; i < 8; i++) {
        int idx = tid + i * 256;
        int r = idx >> 4;
        int c4 = idx & 15;
        pf[i] = x4[r * 32 + 16 + c4];
    }

    const int wrow = (wid & 3) * 32;
    const int wcol = (wid >> 2) * 64;
    const int lq = lane >> 2;
    const int lr = lane & 3;

    float acc[2][8][4];
    #pragma unroll
    for (int m = 0; m < 2; m++)
        #pragma unroll
        for (int n = 0; n < 8; n++)
            #pragma unroll
            for (int j = 0; j < 4; j++) acc[m][n][j] = 0.f;

    compute_chunk(As0, Bs0, acc, wrow, wcol, lq, lr);

    #pragma unroll
    for (int i = 0; i < 8; i++) {
        int idx = tid + i * 256;
        int r = idx >> 4;
        int c4 = idx & 15;
        uint4 u;
        u.x = tf32_rna(pf[i].x); u.y = tf32_rna(pf[i].y);
        u.z = tf32_rna(pf[i].z); u.w = tf32_rna(pf[i].w);
        *reinterpret_cast<uint4*>(As1 + r * CH_STR + c4 * 4) = u;
    }
    __syncthreads();

    compute_chunk(As1, Bs1, acc, wrow, wcol, lq, lr);

    #pragma unroll
    for (int m = 0; m < 2; m++) {
        size_t row = (size_t)(R0 + wrow + m * 16 + lq);
        #pragma unroll
        for (int n = 0; n < 8; n++) {
            int col = wcol + n * 8 + 2 * lr;
            *reinterpret_cast<float2*>(g_xp + row * 128 + col) =
                make_float2(acc[m][n][0], acc[m][n][1]);
            *reinterpret_cast<float2*>(g_xp + (row + 8) * 128 + col) =
                make_float2(acc[m][n][2], acc[m][n][3]);
        }
    }
}

// ---------------------------------------------------------------------------
// CSR build (graph-range parameterized): histogram -> scan -> fill
// ---------------------------------------------------------------------------
__global__ void hist_k(const int* __restrict__ dst, int g0) {
    __shared__ int sh[N_];                 // 40KB
    const int g = g0 + blockIdx.x / HB;
    const int chunk = blockIdx.x % HB;
    const int t = threadIdx.x;
    for (int b = t; b < N_; b += 512) sh[b] = 0;
    __syncthreads();

    const int base_e = g * E_ + chunk * EPB;
    for (int i = t; i < EPB; i += 512) {
        int e = base_e + i;
        g_rank[e] = atomicAdd(&sh[dst[e]], 1);
    }
    __syncthreads();

    for (int b = t; b < N_; b += 512) {
        int c = sh[b];
        sh[b] = (c > 0) ? atomicAdd(&g_deg[g * N_ + b], c) : 0;
    }
    __syncthreads();

    for (int i = t; i < EPB; i += 512) {
        int e = base_e + i;
        g_rank[e] += sh[dst[e]];
    }
}

__global__ void scan_k(int g0) {
    const int g = g0 + blockIdx.x;
    const int t = threadIdx.x;           // 0..1023
    __shared__ int sm[1024];
    const int base = g * N_;
    int loc[10];
    int s = 0;
    if (t < 1000) {
        #pragma unroll
        for (int i = 0; i < 10; i++) {
            loc[i] = g_deg[base + t * 10 + i];
            s += loc[i];
        }
    }
    sm[t] = s;
    __syncthreads();
    #pragma unroll
    for (int off = 1; off < 1024; off <<= 1) {
        int v = (t >= off) ? sm[t - off] : 0;
        __syncthreads();
        sm[t] += v;
        __syncthreads();
    }
    if (t < 1000) {
        int run = (t > 0 ? sm[t - 1] : 0) + g * E_;
        #pragma unroll
        for (int i = 0; i < 10; i++) {
            g_off[base + t * 10 + i] = run;
            run += loc[i];
        }
    }
}

// fill edges of graphs [g0, g0+ngraphs)
__global__ void fill_k(const int4* __restrict__ src4,
                       const int4* __restrict__ dst4, int g0, int ngraphs) {
    int t = blockIdx.x * blockDim.x + threadIdx.x;
    int nq = ngraphs * (E_ / 4);
    if (t >= nq) return;
    int tq = g0 * (E_ / 4) + t;
    int g = (tq * 4) / E_;
    int4 d = dst4[tq];
    int4 s = src4[tq];
    int4 r = reinterpret_cast<const int4*>(g_rank)[tq];
    int b = g * N_;
    g_elist[g_off[b + d.x] + r.x] = s.x;
    g_elist[g_off[b + d.y] + r.y] = s.y;
    g_elist[g_off[b + d.z] + r.z] = s.z;
    g_elist[g_off[b + d.w] + r.w] = s.w;
}

// ---------------------------------------------------------------------------
// Gather + finalize fused: warp per node (node0..node0+ncount).
// ---------------------------------------------------------------------------
__global__ void gather_fin_k(const float* __restrict__ b_sage,
                             int node0, int ncount) {
    int ni = (int)(((long)blockIdx.x * blockDim.x + threadIdx.x) >> 5);
    int lane = threadIdx.x & 31;
    if (ni >= ncount) return;
    int node = node0 + ni;
    int g = node / N_;
    int off = g_off[node];
    int deg = g_deg[node];
    const float* xpn = g_xp + 64 + lane * 2;   // neigh half
    size_t gbase = (size_t)g * N_;

    float sx = 0.f, sy = 0.f;
    int i = 0;
    for (; i + 8 <= deg; i += 8) {
        float2 v[8];
        #pragma unroll
        for (int j = 0; j < 8; j++) {
            int s = g_elist[off + i + j];
            v[j] = *reinterpret_cast<const float2*>(xpn + (gbase + s) * 128);
        }
        #pragma unroll
        for (int j = 0; j < 8; j++) { sx += v[j].x; sy += v[j].y; }
    }
    for (; i + 4 <= deg; i += 4) {
        float2 v[4];
        #pragma unroll
        for (int j = 0; j < 4; j++) {
            int s = g_elist[off + i + j];
            v[j] = *reinterpret_cast<const float2*>(xpn + (gbase + s) * 128);
        }
        #pragma unroll
        for (int j = 0; j < 4; j++) { sx += v[j].x; sy += v[j].y; }
    }
    for (; i < deg; i++) {
        int s0 = g_elist[off + i];
        float2 v0 = *reinterpret_cast<const float2*>(xpn + (gbase + s0) * 128);
        sx += v0.x;
        sy += v0.y;
    }

    float inv = 1.f / fmaxf((float)deg, 1.f);
    float2 self = *reinterpret_cast<const float2*>(
        g_xp + (size_t)node * 128 + lane * 2);
    float2 bs = *reinterpret_cast<const float2*>(b_sage + lane * 2);
    float h0 = self.x + sx * inv + bs.x;
    float h1 = self.y + sy * inv + bs.y;
    float ss = h0 * h0 + h1 * h1;
    #pragma unroll
    for (int o = 16; o > 0; o >>= 1)
        ss += __shfl_xor_sync(0xFFFFFFFFu, ss, o);
    float sc = 1.f / fmaxf(sqrtf(ss), 1e-12f);
    float2 outv = make_float2(h0 * sc, h1 * sc);
    *reinterpret_cast<float2*>(g_acc + (size_t)node * 64 + lane * 2) = outv;
}

// ---------------------------------------------------------------------------
// Attention: warp per pair.
// ---------------------------------------------------------------------------
__device__ __forceinline__ float fsigmoid(float x) {
    float t;
    asm("tanh.approx.f32 %0, %1;" : "=f"(t) : "f"(0.5f * x));
    return fmaf(0.5f, t, 0.5f);
}

__global__ void attn_k(const int* __restrict__ idx,
                       const float* __restrict__ w_ff2,
                       const float* __restrict__ b_ff2,
                       const float* __restrict__ w_ff1,
                       const float* __restrict__ b_ff1,
                       const float* __restrict__ w_out,
                       float* __restrict__ out) {
    int p = (int)(((long)blockIdx.x * blockDim.x + threadIdx.x) >> 5);
    int lane = threadIdx.x & 31;
    if (p >= P_) return;
    const int cb = lane * 4;

    float w2[4], wo[4];
    #pragma unroll
    for (int j = 0; j < 4; j++) { w2[j] = w_ff2[cb + j]; wo[j] = w_out[cb + j]; }
    const float bf2 = *b_ff2;
    const float bf1 = *b_ff1;

    float tv[T_][4];
    #pragma unroll
    for (int t = 0; t < T_; t++) {
        int i0 = idx[t * P_ + p];
        int i1 = idx[T_ * P_ + t * P_ + p];
        const float* row = (lane < 16)
            ? g_acc + ((size_t)(t * N_ + i0)) * 64 + cb
            : g_acc + ((size_t)((T_ + t) * N_ + i1)) * 64 + (cb - 64);
        float4 v = *reinterpret_cast<const float4*>(row);
        tv[t][0] = v.x; tv[t][1] = v.y; tv[t][2] = v.z; tv[t][3] = v.w;
    }

    float u[T_];
    #pragma unroll
    for (int t = 0; t < T_; t++) {
        float s = tv[t][0] * w2[0];
        s = fmaf(tv[t][1], w2[1], s);
        s = fmaf(tv[t][2], w2[2], s);
        s = fmaf(tv[t][3], w2[3], s);
        u[t] = s;
    }
    #pragma unroll
    for (int off = 16; off > 0; off >>= 1)
        #pragma unroll
        for (int t = 0; t < T_; t++)
            u[t] += __shfl_xor_sync(0xFFFFFFFFu, u[t], off);

    float s0 = 0.f, s1 = 0.f, s2 = 0.f;
    #pragma unroll
    for (int t = 0; t < T_; t++) {
        float wf = w_ff1[t];
        float d0 = u[t] - (t > 0 ? u[t - 1] : 0.f);
        float d1 = u[t] - (t > 1 ? u[t - 2] : 0.f);
        float d2 = u[t] - (t > 2 ? u[t - 3] : 0.f);
        s0 = fmaf(fmaxf(d0 + bf2, 0.f), wf, s0);
        s1 = fmaf(fmaxf(d1 + bf2, 0.f), wf, s1);
        s2 = fmaf(fmaxf(d2 + bf2, 0.f), wf, s2);
    }
    s0 += bf1; s1 += bf1; s2 += bf1;
    float mx = fmaxf(s0, fmaxf(s1, s2));
    float e0 = __expf(s0 - mx), e1 = __expf(s1 - mx), e2 = __expf(s2 - mx);
    float inv = 1.f / (e0 + e1 + e2);
    float sw[3] = {e0 * inv, e1 * inv, e2 * inv};

    float o[T_];
    #pragma unroll
    for (int t = 0; t < T_; t++) {
        float acc = 0.f;
        #pragma unroll
        for (int j = 0; j < 4; j++) {
            float att = 0.f;
            #pragma unroll
            for (int km = 0; km < 3; km++) {
                float d = tv[t][j] - (t > km ? tv[t - km - 1][j] : 0.f);
                att = fmaf(sw[km], fsigmoid(d), att);
            }
            acc = fmaf(tv[t][j] * att, wo[j], acc);
        }
        o[t] = acc;
    }
    #pragma unroll
    for (int off = 16; off > 0; off >>= 1)
        #pragma unroll
        for (int t = 0; t < T_; t++)
            o[t] += __shfl_xor_sync(0xFFFFFFFFu, o[t], off);

    if (lane == 0) {
        #pragma unroll
        for (int t = 0; t < T_; t++)
            out[t * P_ + p] = o[t];
    }
}

// ---------------------------------------------------------------------------
extern "C" void kernel_launch(void* const* d_in, const int* in_sizes, int n_in,
                              void* d_out, int out_size) {
    const float* x       = (const float*)d_in[0];
    const int*   src     = (const int*)  d_in[1];
    const int*   dst     = (const int*)  d_in[2];
    const int*   idx     = (const int*)  d_in[3];
    const float* w_self  = (const float*)d_in[4];
    const float* w_neigh = (const float*)d_in[5];
    const float* b_sage  = (const float*)d_in[6];
    const float* w_ff2   = (const float*)d_in[7];
    const float* b_ff2   = (const float*)d_in[8];
    const float* w_ff1   = (const float*)d_in[9];
    const float* b_ff1   = (const float*)d_in[10];
    const float* w_out   = (const float*)d_in[11];
    float* out = (float*)d_out;

    static cudaStream_t s2 = nullptr, s3 = nullptr;
    static cudaEvent_t evFork = nullptr, evCSRB = nullptr, evGA = nullptr,
                       evGB1 = nullptr, evGB2 = nullptr, evGath = nullptr;
    if (!s2) {
        cudaStreamCreate(&s2);
        cudaStreamCreate(&s3);
        cudaEventCreateWithFlags(&evFork, cudaEventDisableTiming);
        cudaEventCreateWithFlags(&evCSRB, cudaEventDisableTiming);
        cudaEventCreateWithFlags(&evGA, cudaEventDisableTiming);
        cudaEventCreateWithFlags(&evGB1, cudaEventDisableTiming);
        cudaEventCreateWithFlags(&evGB2, cudaEventDisableTiming);
        cudaEventCreateWithFlags(&evGath, cudaEventDisableTiming);
        cudaFuncSetAttribute(gemm_mma, cudaFuncAttributeMaxDynamicSharedMemorySize,
                             SMEM_GEMM);
    }

    void* degPtr = nullptr; cudaGetSymbolAddress(&degPtr, g_deg);

    // Fork both side streams immediately.
    cudaEventRecord(evFork, 0);
    cudaStreamWaitEvent(s2, evFork, 0);
    cudaStreamWaitEvent(s3, evFork, 0);

    // per-half deg clears
    cudaMemsetAsync(degPtr, 0, (size_t)120000 * sizeof(int), s2);
    cudaMemsetAsync((char*)degPtr + (size_t)120000 * sizeof(int), 0,
                    (size_t)120000 * sizeof(int), s3);

    // s0: B prep
    b_prep<<<64, 256>>>(w_self, w_neigh);

    // s2: CSR half A (graphs 0..11)
    hist_k<<<12 * HB, 512, 0, s2>>>(dst, 0);
    scan_k<<<12, 1024, 0, s2>>>(0);
    int fillb = (12 * (E_ / 4) + 255) / 256;
    fill_k<<<fillb, 256, 0, s2>>>((const int4*)src, (const int4*)dst, 0, 12);

    // s3: CSR half B (graphs 12..23)
    hist_k<<<12 * HB, 512, 0, s3>>>(dst, 12);
    scan_k<<<12, 1024, 0, s3>>>(12);
    fill_k<<<fillb, 256, 0, s3>>>((const int4*)src, (const int4*)dst, 12, 12);
    cudaEventRecord(evCSRB, s3);

    // s0: GEMM pieces
    gemm_mma<<<TILES_A, 256, SMEM_GEMM>>>(x, 0);
    cudaEventRecord(evGA, 0);
    gemm_mma<<<TILES_B1, 256, SMEM_GEMM>>>(x, TILES_A);
    cudaEventRecord(evGB1, 0);
    gemm_mma<<<TILES_B2, 256, SMEM_GEMM>>>(x, TILES_A + TILES_B1);
    cudaEventRecord(evGB2, 0);
    gemm_mma<<<TILES_B3, 256, SMEM_GEMM>>>(x, TILES_A + TILES_B1 + TILES_B2);

    // s2 gather ladder (in-order after fillA)
    cudaStreamWaitEvent(s2, evGA, 0);
    gather_fin_k<<<(120000 * 32 + 255) / 256, 256, 0, s2>>>(b_sage, 0, 120000);
    cudaStreamWaitEvent(s2, evGB1, 0);
    cudaStreamWaitEvent(s2, evCSRB, 0);
    gather_fin_k<<<(60000 * 32 + 255) / 256, 256, 0, s2>>>(b_sage, 120000, 60000);
    cudaStreamWaitEvent(s2, evGB2, 0);
    gather_fin_k<<<(40000 * 32 + 255) / 256, 256, 0, s2>>>(b_sage, 180000, 40000);
    cudaEventRecord(evGath, s2);

    // s0: small exposed gather tail (after gemmB3 in-order; needs CSR-B)
    cudaStreamWaitEvent(0, evCSRB, 0);
    gather_fin_k<<<(20000 * 32 + 255) / 256, 256>>>(b_sage, 220000, 20000);

    // join: attn needs all gathers
    cudaStreamWaitEvent(0, evGath, 0);
    attn_k<<<(P_ * 32 + 255) / 256, 256>>>(idx, w_ff2, b_ff2, w_ff1, b_ff1,
                                           w_out, out);
}

// round 17
// speedup vs baseline: 1.0281x; 1.0281x over previous
#include <cuda_runtime.h>
#include <cuda_bf16.h>
#include <cstdint>

#define T_ 12
#define N_ 10000
#define E_ 160000
#define P_ 30000
#define DIN_ 128
#define H_ 64
#define NG 24            // 2*T graphs
#define M_ (NG * N_)     // 240000 rows
#define NE_ALL (NG * E_) // 3,840,000 edges
#define HB 8             // hist blocks per graph
#define EPB (E_ / HB)    // 20000 edges per hist block

#define NTILES (M_ / 128)     // 1875
#define TILES_A 938           // rows ..120063  (covers graphs 0..11)
#define TILES_B1 469          // rows ..180095  (covers graphs 12..17)
#define TILES_B2 312          // rows ..220031  (covers graphs 18..21)
#define TILES_B3 (NTILES - TILES_A - TILES_B1 - TILES_B2)   // 156

typedef unsigned long long u64;

// Scratch (allocation-free rule: __device__ globals)
__device__ float    g_xps[(size_t)M_ * 64];  // self half, fp32
__device__ uint32_t g_xpn[(size_t)M_ * 32];  // neighbor half, bf16x2 (2 ch/word)
__device__ float    g_acc[(size_t)M_ * 64];  // normalized h
__device__ int      g_deg[M_];
__device__ int      g_off[M_];               // CSR start (incl. g*E_ base)
__device__ int      g_rank[NE_ALL];          // edge's final rank in dst bucket
__device__ int      g_elist[NE_ALL];         // src node id per CSR slot
__device__ uint32_t g_Bt[128 * 128];         // B^T as [n][k], tf32-rounded bits

__device__ __forceinline__ uint32_t tf32_rna(float f) {
    uint32_t u;
    asm("cvt.rna.tf32.f32 %0, %1;" : "=r"(u) : "f"(f));
    return u;
}
__device__ __forceinline__ uint32_t pack_bf16x2(float lo, float hi) {
    uint32_t w;
    asm("cvt.rn.bf16x2.f32 %0, %1, %2;" : "=r"(w) : "f"(hi), "f"(lo));
    return w;
}

// ---------------------------------------------------------------------------
// B prep: g_Bt[n][k] = tf32(W[k][n])
// ---------------------------------------------------------------------------
__global__ void b_prep(const float* __restrict__ w_self,
                       const float* __restrict__ w_neigh) {
    int idx = blockIdx.x * blockDim.x + threadIdx.x;   // 0..16383
    int n = idx >> 7;
    int k = idx & 127;
    const float* wsrc = (n < 64) ? (w_self + n) : (w_neigh + (n - 64));
    g_Bt[n * 128 + k] = tf32_rna(wsrc[k * 64]);
}

// ---------------------------------------------------------------------------
// tf32 mma.sync GEMM: 128x128 tile/CTA, 8 warps, warp tile 32x64,
// k-chunk (64) double-buffered. Epilogue: self half fp32, neigh half bf16x2.
// ---------------------------------------------------------------------------
#define CH_STR 68
#define SMEM_GEMM (4 * 128 * CH_STR * 4)   // 139264 B

__device__ __forceinline__ void compute_chunk(
    const uint32_t* __restrict__ As, const uint32_t* __restrict__ Bs,
    float acc[2][8][4], int wrow, int wcol, int lq, int lr) {
    #pragma unroll
    for (int ks = 0; ks < 8; ks++) {
        const int kc = ks * 8 + lr;
        uint32_t a[2][4];
        #pragma unroll
        for (int m = 0; m < 2; m++) {
            int rbase = wrow + m * 16 + lq;
            a[m][0] = As[rbase * CH_STR + kc];
            a[m][1] = As[(rbase + 8) * CH_STR + kc];
            a[m][2] = As[rbase * CH_STR + kc + 4];
            a[m][3] = As[(rbase + 8) * CH_STR + kc + 4];
        }
        uint32_t b[8][2];
        #pragma unroll
        for (int n = 0; n < 8; n++) {
            int nrow = wcol + n * 8 + lq;
            b[n][0] = Bs[nrow * CH_STR + kc];
            b[n][1] = Bs[nrow * CH_STR + kc + 4];
        }
        #pragma unroll
        for (int m = 0; m < 2; m++)
            #pragma unroll
            for (int n = 0; n < 8; n++) {
                asm volatile(
                    "mma.sync.aligned.m16n8k8.row.col.f32.tf32.tf32.f32 "
                    "{%0,%1,%2,%3}, {%4,%5,%6,%7}, {%8,%9}, {%0,%1,%2,%3};"
                    : "+f"(acc[m][n][0]), "+f"(acc[m][n][1]),
                      "+f"(acc[m][n][2]), "+f"(acc[m][n][3])
                    : "r"(a[m][0]), "r"(a[m][1]), "r"(a[m][2]), "r"(a[m][3]),
                      "r"(b[n][0]), "r"(b[n][1]));
            }
    }
}

__global__ __launch_bounds__(256, 1)
void gemm_mma(const float* __restrict__ x, int tile0) {
    extern __shared__ uint32_t smem[];
    uint32_t* As0 = smem;
    uint32_t* As1 = smem + 128 * CH_STR;
    uint32_t* Bs0 = smem + 2 * 128 * CH_STR;
    uint32_t* Bs1 = smem + 3 * 128 * CH_STR;
    const int tid = threadIdx.x;
    const int wid = tid >> 5;
    const int lane = tid & 31;
    const int R0 = (tile0 + blockIdx.x) * 128;

    const float4* x4 = reinterpret_cast<const float4*>(x) + (size_t)R0 * 32;

    {
        const uint4* b4 = reinterpret_cast<const uint4*>(g_Bt);
        #pragma unroll
        for (int i = 0; i < 16; i++) {
            int idx = tid + i * 256;
            int n = idx >> 5;
            int c4 = idx & 31;
            uint4 v = b4[idx];
            uint32_t* dst = (c4 < 16) ? Bs0 : Bs1;
            *reinterpret_cast<uint4*>(dst + n * CH_STR + (c4 & 15) * 4) = v;
        }
    }
    {
        #pragma unroll
        for (int i = 0; i < 8; i++) {
            int idx = tid + i * 256;
            int r = idx >> 4;
            int c4 = idx & 15;
            float4 v = x4[r * 32 + c4];
            uint4 u;
            u.x = tf32_rna(v.x); u.y = tf32_rna(v.y);
            u.z = tf32_rna(v.z); u.w = tf32_rna(v.w);
            *reinterpret_cast<uint4*>(As0 + r * CH_STR + c4 * 4) = u;
        }
    }
    __syncthreads();

    float4 pf[8];
    #pragma unroll
    for (int i = 0; i < 8; i++) {
        int idx = tid + i * 256;
        int r = idx >> 4;
        int c4 = idx & 15;
        pf[i] = x4[r * 32 + 16 + c4];
    }

    const int wrow = (wid & 3) * 32;
    const int wcol = (wid >> 2) * 64;   // 0 = self half, 64 = neighbor half
    const int lq = lane >> 2;
    const int lr = lane & 3;

    float acc[2][8][4];
    #pragma unroll
    for (int m = 0; m < 2; m++)
        #pragma unroll
        for (int n = 0; n < 8; n++)
            #pragma unroll
            for (int j = 0; j < 4; j++) acc[m][n][j] = 0.f;

    compute_chunk(As0, Bs0, acc, wrow, wcol, lq, lr);

    #pragma unroll
    for (int i = 0; i < 8; i++) {
        int idx = tid + i * 256;
        int r = idx >> 4;
        int c4 = idx & 15;
        uint4 u;
        u.x = tf32_rna(pf[i].x); u.y = tf32_rna(pf[i].y);
        u.z = tf32_rna(pf[i].z); u.w = tf32_rna(pf[i].w);
        *reinterpret_cast<uint4*>(As1 + r * CH_STR + c4 * 4) = u;
    }
    __syncthreads();

    compute_chunk(As1, Bs1, acc, wrow, wcol, lq, lr);

    // epilogue
    if (wcol == 0) {
        // self half -> fp32 g_xps[row][col]
        #pragma unroll
        for (int m = 0; m < 2; m++) {
            size_t row = (size_t)(R0 + wrow + m * 16 + lq);
            #pragma unroll
            for (int n = 0; n < 8; n++) {
                int col = n * 8 + 2 * lr;
                *reinterpret_cast<float2*>(g_xps + row * 64 + col) =
                    make_float2(acc[m][n][0], acc[m][n][1]);
                *reinterpret_cast<float2*>(g_xps + (row + 8) * 64 + col) =
                    make_float2(acc[m][n][2], acc[m][n][3]);
            }
        }
    } else {
        // neighbor half -> bf16x2 g_xpn[row][(col-64)/2]
        #pragma unroll
        for (int m = 0; m < 2; m++) {
            size_t row = (size_t)(R0 + wrow + m * 16 + lq);
            #pragma unroll
            for (int n = 0; n < 8; n++) {
                int w = n * 4 + lr;   // word index 0..31
                g_xpn[row * 32 + w]       = pack_bf16x2(acc[m][n][0], acc[m][n][1]);
                g_xpn[(row + 8) * 32 + w] = pack_bf16x2(acc[m][n][2], acc[m][n][3]);
            }
        }
    }
}

// ---------------------------------------------------------------------------
// CSR build: privatized-smem histogram producing per-edge final rank.
// ---------------------------------------------------------------------------
__global__ void hist_k(const int* __restrict__ dst) {
    __shared__ int sh[N_];                 // 40KB
    const int g = blockIdx.x / HB;
    const int chunk = blockIdx.x % HB;
    const int t = threadIdx.x;
    for (int b = t; b < N_; b += 512) sh[b] = 0;
    __syncthreads();

    const int base_e = g * E_ + chunk * EPB;
    for (int i = t; i < EPB; i += 512) {
        int e = base_e + i;
        g_rank[e] = atomicAdd(&sh[dst[e]], 1);
    }
    __syncthreads();

    for (int b = t; b < N_; b += 512) {
        int c = sh[b];
        sh[b] = (c > 0) ? atomicAdd(&g_deg[g * N_ + b], c) : 0;
    }
    __syncthreads();

    for (int i = t; i < EPB; i += 512) {
        int e = base_e + i;
        g_rank[e] += sh[dst[e]];
    }
}

__global__ void scan_k() {
    const int g = blockIdx.x;
    const int t = threadIdx.x;           // 0..1023
    __shared__ int sm[1024];
    const int base = g * N_;
    int loc[10];
    int s = 0;
    if (t < 1000) {
        #pragma unroll
        for (int i = 0; i < 10; i++) {
            loc[i] = g_deg[base + t * 10 + i];
            s += loc[i];
        }
    }
    sm[t] = s;
    __syncthreads();
    #pragma unroll
    for (int off = 1; off < 1024; off <<= 1) {
        int v = (t >= off) ? sm[t - off] : 0;
        __syncthreads();
        sm[t] += v;
        __syncthreads();
    }
    if (t < 1000) {
        int run = (t > 0 ? sm[t - 1] : 0) + g * E_;
        #pragma unroll
        for (int i = 0; i < 10; i++) {
            g_off[base + t * 10 + i] = run;
            run += loc[i];
        }
    }
}

__global__ void fill_k(const int4* __restrict__ src4,
                       const int4* __restrict__ dst4) {
    int t = blockIdx.x * blockDim.x + threadIdx.x;
    if (t >= NE_ALL / 4) return;
    int g = (t * 4) / E_;                   // E_ % 4 == 0
    int4 d = dst4[t];
    int4 s = src4[t];
    int4 r = reinterpret_cast<const int4*>(g_rank)[t];
    int b = g * N_;
    g_elist[g_off[b + d.x] + r.x] = s.x;
    g_elist[g_off[b + d.y] + r.y] = s.y;
    g_elist[g_off[b + d.z] + r.z] = s.z;
    g_elist[g_off[b + d.w] + r.w] = s.w;
}

// ---------------------------------------------------------------------------
// Gather + finalize fused: warp per node, lane -> bf16x2 word (2 channels).
// ---------------------------------------------------------------------------
__global__ void gather_fin_k(const float* __restrict__ b_sage,
                             int node0, int ncount) {
    int ni = (int)(((long)blockIdx.x * blockDim.x + threadIdx.x) >> 5);
    int lane = threadIdx.x & 31;
    if (ni >= ncount) return;
    int node = node0 + ni;
    int g = node / N_;
    int off = g_off[node];
    int deg = g_deg[node];
    const uint32_t* xpn = g_xpn + lane;       // + row*32
    size_t gbase = (size_t)g * N_;

    float sx = 0.f, sy = 0.f;
    int i = 0;
    for (; i + 8 <= deg; i += 8) {
        uint32_t w[8];
        #pragma unroll
        for (int j = 0; j < 8; j++) {
            int s = g_elist[off + i + j];
            w[j] = xpn[(gbase + s) * 32];
        }
        #pragma unroll
        for (int j = 0; j < 8; j++) {
            sx += __uint_as_float(w[j] << 16);
            sy += __uint_as_float(w[j] & 0xFFFF0000u);
        }
    }
    for (; i + 4 <= deg; i += 4) {
        uint32_t w[4];
        #pragma unroll
        for (int j = 0; j < 4; j++) {
            int s = g_elist[off + i + j];
            w[j] = xpn[(gbase + s) * 32];
        }
        #pragma unroll
        for (int j = 0; j < 4; j++) {
            sx += __uint_as_float(w[j] << 16);
            sy += __uint_as_float(w[j] & 0xFFFF0000u);
        }
    }
    for (; i < deg; i++) {
        int s = g_elist[off + i];
        uint32_t w = xpn[(gbase + s) * 32];
        sx += __uint_as_float(w << 16);
        sy += __uint_as_float(w & 0xFFFF0000u);
    }

    float inv = 1.f / fmaxf((float)deg, 1.f);
    float2 self = *reinterpret_cast<const float2*>(
        g_xps + (size_t)node * 64 + lane * 2);
    float2 bs = *reinterpret_cast<const float2*>(b_sage + lane * 2);
    float h0 = self.x + sx * inv + bs.x;
    float h1 = self.y + sy * inv + bs.y;
    float ss = h0 * h0 + h1 * h1;
    #pragma unroll
    for (int o = 16; o > 0; o >>= 1)
        ss += __shfl_xor_sync(0xFFFFFFFFu, ss, o);
    float sc = 1.f / fmaxf(sqrtf(ss), 1e-12f);
    float2 outv = make_float2(h0 * sc, h1 * sc);
    *reinterpret_cast<float2*>(g_acc + (size_t)node * 64 + lane * 2) = outv;
}

// ---------------------------------------------------------------------------
// Attention: warp per pair.
// ---------------------------------------------------------------------------
__device__ __forceinline__ float fsigmoid(float x) {
    float t;
    asm("tanh.approx.f32 %0, %1;" : "=f"(t) : "f"(0.5f * x));
    return fmaf(0.5f, t, 0.5f);
}

__global__ void attn_k(const int* __restrict__ idx,
                       const float* __restrict__ w_ff2,
                       const float* __restrict__ b_ff2,
                       const float* __restrict__ w_ff1,
                       const float* __restrict__ b_ff1,
                       const float* __restrict__ w_out,
                       float* __restrict__ out) {
    int p = (int)(((long)blockIdx.x * blockDim.x + threadIdx.x) >> 5);
    int lane = threadIdx.x & 31;
    if (p >= P_) return;
    const int cb = lane * 4;

    float w2[4], wo[4];
    #pragma unroll
    for (int j = 0; j < 4; j++) { w2[j] = w_ff2[cb + j]; wo[j] = w_out[cb + j]; }
    const float bf2 = *b_ff2;
    const float bf1 = *b_ff1;

    float tv[T_][4];
    #pragma unroll
    for (int t = 0; t < T_; t++) {
        int i0 = idx[t * P_ + p];
        int i1 = idx[T_ * P_ + t * P_ + p];
        const float* row = (lane < 16)
            ? g_acc + ((size_t)(t * N_ + i0)) * 64 + cb
            : g_acc + ((size_t)((T_ + t) * N_ + i1)) * 64 + (cb - 64);
        float4 v = *reinterpret_cast<const float4*>(row);
        tv[t][0] = v.x; tv[t][1] = v.y; tv[t][2] = v.z; tv[t][3] = v.w;
    }

    float u[T_];
    #pragma unroll
    for (int t = 0; t < T_; t++) {
        float s = tv[t][0] * w2[0];
        s = fmaf(tv[t][1], w2[1], s);
        s = fmaf(tv[t][2], w2[2], s);
        s = fmaf(tv[t][3], w2[3], s);
        u[t] = s;
    }
    #pragma unroll
    for (int off = 16; off > 0; off >>= 1)
        #pragma unroll
        for (int t = 0; t < T_; t++)
            u[t] += __shfl_xor_sync(0xFFFFFFFFu, u[t], off);

    float s0 = 0.f, s1 = 0.f, s2 = 0.f;
    #pragma unroll
    for (int t = 0; t < T_; t++) {
        float wf = w_ff1[t];
        float d0 = u[t] - (t > 0 ? u[t - 1] : 0.f);
        float d1 = u[t] - (t > 1 ? u[t - 2] : 0.f);
        float d2 = u[t] - (t > 2 ? u[t - 3] : 0.f);
        s0 = fmaf(fmaxf(d0 + bf2, 0.f), wf, s0);
        s1 = fmaf(fmaxf(d1 + bf2, 0.f), wf, s1);
        s2 = fmaf(fmaxf(d2 + bf2, 0.f), wf, s2);
    }
    s0 += bf1; s1 += bf1; s2 += bf1;
    float mx = fmaxf(s0, fmaxf(s1, s2));
    float e0 = __expf(s0 - mx), e1 = __expf(s1 - mx), e2 = __expf(s2 - mx);
    float inv = 1.f / (e0 + e1 + e2);
    float sw[3] = {e0 * inv, e1 * inv, e2 * inv};

    float o[T_];
    #pragma unroll
    for (int t = 0; t < T_; t++) {
        float acc = 0.f;
        #pragma unroll
        for (int j = 0; j < 4; j++) {
            float att = 0.f;
            #pragma unroll
            for (int km = 0; km < 3; km++) {
                float d = tv[t][j] - (t > km ? tv[t - km - 1][j] : 0.f);
                att = fmaf(sw[km], fsigmoid(d), att);
            }
            acc = fmaf(tv[t][j] * att, wo[j], acc);
        }
        o[t] = acc;
    }
    #pragma unroll
    for (int off = 16; off > 0; off >>= 1)
        #pragma unroll
        for (int t = 0; t < T_; t++)
            o[t] += __shfl_xor_sync(0xFFFFFFFFu, o[t], off);

    if (lane == 0) {
        #pragma unroll
        for (int t = 0; t < T_; t++)
            out[t * P_ + p] = o[t];
    }
}

// ---------------------------------------------------------------------------
extern "C" void kernel_launch(void* const* d_in, const int* in_sizes, int n_in,
                              void* d_out, int out_size) {
    const float* x       = (const float*)d_in[0];
    const int*   src     = (const int*)  d_in[1];
    const int*   dst     = (const int*)  d_in[2];
    const int*   idx     = (const int*)  d_in[3];
    const float* w_self  = (const float*)d_in[4];
    const float* w_neigh = (const float*)d_in[5];
    const float* b_sage  = (const float*)d_in[6];
    const float* w_ff2   = (const float*)d_in[7];
    const float* b_ff2   = (const float*)d_in[8];
    const float* w_ff1   = (const float*)d_in[9];
    const float* b_ff1   = (const float*)d_in[10];
    const float* w_out   = (const float*)d_in[11];
    float* out = (float*)d_out;

    static cudaStream_t s2 = nullptr;
    static cudaEvent_t evFork = nullptr, evCSR = nullptr, evGA = nullptr,
                       evGB1 = nullptr, evGB2 = nullptr, evGath = nullptr;
    if (!s2) {
        cudaStreamCreate(&s2);
        cudaEventCreateWithFlags(&evFork, cudaEventDisableTiming);
        cudaEventCreateWithFlags(&evCSR, cudaEventDisableTiming);
        cudaEventCreateWithFlags(&evGA, cudaEventDisableTiming);
        cudaEventCreateWithFlags(&evGB1, cudaEventDisableTiming);
        cudaEventCreateWithFlags(&evGB2, cudaEventDisableTiming);
        cudaEventCreateWithFlags(&evGath, cudaEventDisableTiming);
        cudaFuncSetAttribute(gemm_mma, cudaFuncAttributeMaxDynamicSharedMemorySize,
                             SMEM_GEMM);
    }

    void* degPtr = nullptr; cudaGetSymbolAddress(&degPtr, g_deg);

    // Fork s2 immediately (CSR chain is independent of b_prep/gemm).
    cudaEventRecord(evFork, 0);
    cudaStreamWaitEvent(s2, evFork, 0);
    cudaMemsetAsync(degPtr, 0, (size_t)M_ * sizeof(int), s2);

    // kernel submission #1
    b_prep<<<64, 256>>>(w_self, w_neigh);
    // #2, #3 on s2
    hist_k<<<NG * HB, 512, 0, s2>>>(dst);
    scan_k<<<NG, 1024, 0, s2>>>();
    // #4: gemmA  (ncu capture slot)
    gemm_mma<<<TILES_A, 256, SMEM_GEMM>>>(x, 0);
    cudaEventRecord(evGA, 0);
    // #5: fill on s2
    int e4blocks = (NE_ALL / 4 + 255) / 256;
    fill_k<<<e4blocks, 256, 0, s2>>>((const int4*)src, (const int4*)dst);
    cudaEventRecord(evCSR, s2);

    // remaining gemm pieces on s0
    gemm_mma<<<TILES_B1, 256, SMEM_GEMM>>>(x, TILES_A);
    cudaEventRecord(evGB1, 0);
    gemm_mma<<<TILES_B2, 256, SMEM_GEMM>>>(x, TILES_A + TILES_B1);
    cudaEventRecord(evGB2, 0);
    gemm_mma<<<TILES_B3, 256, SMEM_GEMM>>>(x, TILES_A + TILES_B1 + TILES_B2);

    // s2 gather ladder (in-order after fill)
    cudaStreamWaitEvent(s2, evGA, 0);
    gather_fin_k<<<(120000 * 32 + 255) / 256, 256, 0, s2>>>(b_sage, 0, 120000);
    cudaStreamWaitEvent(s2, evGB1, 0);
    gather_fin_k<<<(60000 * 32 + 255) / 256, 256, 0, s2>>>(b_sage, 120000, 60000);
    cudaStreamWaitEvent(s2, evGB2, 0);
    gather_fin_k<<<(40000 * 32 + 255) / 256, 256, 0, s2>>>(b_sage, 180000, 40000);
    cudaEventRecord(evGath, s2);

    // s0: small exposed gather tail (after gemmB3 in-order; needs CSR)
    cudaStreamWaitEvent(0, evCSR, 0);
    gather_fin_k<<<(20000 * 32 + 255) / 256, 256>>>(b_sage, 220000, 20000);

    // join: attn needs all gathers
    cudaStreamWaitEvent(0, evGath, 0);
    attn_k<<<(P_ * 32 + 255) / 256, 256>>>(idx, w_ff2, b_ff2, w_ff1, b_ff1,
                                           w_out, out);
}